// round 1
// baseline (speedup 1.0000x reference)
#include <cuda_runtime.h>
#include <cmath>

// Problem constants
#define LSTEPS 47      // L = R + O - 1
#define RR 24          // Water2sea_slice_num (recurrence rows)
#define OO 24          // Original_slice_len
#define BB 64          // batch
#define EMB 128
#define HH 256
#define M1 1536        // RR * BB
#define MALL 72192     // LSTEPS * M1

// output_all floats: M1 * LSTEPS * 2H = 1536*47*512
#define OUT_ALL_ELEMS 36962304
#define HID_ELEMS 393216   // BB * 24 * HH

// Scratch (device globals; allocation inside kernel_launch is forbidden)
__device__ float d_a[MALL * EMB];            // x for all steps   (36.9 MB)
__device__ float d_qkv[MALL * 3 * EMB];      // qkv               (110.9 MB)
__device__ float d_att[MALL * EMB];          // attention output  (36.9 MB)
__device__ float d_y[MALL * EMB];            // MHA output        (36.9 MB)
__device__ float d_pre[(size_t)MALL * 1536]; // precomputed x/y contribution (443.5 MB)
__device__ float d_h[2 * M1 * 512];          // ping-pong [h_row|h_col]
__device__ float d_g[M1 * 1536];             // per-step gate pre-activation

// ---------------------------------------------------------------------------
// build x for all steps: a[l,r,b,i] = input[b, l-r, r, i] if 0<=l-r<OO else 0
// ---------------------------------------------------------------------------
__global__ void build_x_kernel(const float* __restrict__ input, float* __restrict__ a) {
    int idx = blockIdx.x * 256 + threadIdx.x;
    if (idx >= MALL * EMB) return;
    int i = idx & 127;
    int m = idx >> 7;          // (l*RR + r)*BB + b
    int b = m & 63;
    int t = m >> 6;
    int r = t % RR;
    int l = t / RR;
    int o = l - r;
    a[idx] = (o >= 0 && o < OO) ? input[((b * OO + o) * RR + r) * EMB + i] : 0.f;
}

// ---------------------------------------------------------------------------
// Generic fp32 GEMM: C[m, n] = sum_k A[m*lda+k] * B[n*ldb+k] (+Cinit)(+bias[n])
// All of M, N multiples of 64; K multiple of 16. No bounds checks.
// ---------------------------------------------------------------------------
__global__ __launch_bounds__(256)
void gemm_tn(const float* __restrict__ A, int lda,
             const float* __restrict__ Bw, int ldb,
             const float* __restrict__ bias,
             const float* __restrict__ Cinit,
             float* __restrict__ C, int ldc,
             int K) {
    __shared__ float As[16][64];
    __shared__ float Bs[16][64];
    int tid = threadIdx.x;
    int tx = tid & 15;          // -> n
    int ty = tid >> 4;          // -> m
    int m0 = blockIdx.y * 64;
    int n0 = blockIdx.x * 64;

    int lrow = tid >> 2;        // 0..63
    int lcol = (tid & 3) << 2;  // 0,4,8,12

    float acc[4][4];
#pragma unroll
    for (int i = 0; i < 4; ++i)
#pragma unroll
        for (int j = 0; j < 4; ++j) acc[i][j] = 0.f;

    for (int k0 = 0; k0 < K; k0 += 16) {
        float4 av = *(const float4*)&A[(size_t)(m0 + lrow) * lda + k0 + lcol];
        float4 bv = *(const float4*)&Bw[(size_t)(n0 + lrow) * ldb + k0 + lcol];
        As[lcol + 0][lrow] = av.x; As[lcol + 1][lrow] = av.y;
        As[lcol + 2][lrow] = av.z; As[lcol + 3][lrow] = av.w;
        Bs[lcol + 0][lrow] = bv.x; Bs[lcol + 1][lrow] = bv.y;
        Bs[lcol + 2][lrow] = bv.z; Bs[lcol + 3][lrow] = bv.w;
        __syncthreads();
#pragma unroll
        for (int kk = 0; kk < 16; ++kk) {
            float ar[4], br[4];
#pragma unroll
            for (int i = 0; i < 4; ++i) ar[i] = As[kk][(ty << 2) + i];
#pragma unroll
            for (int j = 0; j < 4; ++j) br[j] = Bs[kk][(tx << 2) + j];
#pragma unroll
            for (int i = 0; i < 4; ++i)
#pragma unroll
                for (int j = 0; j < 4; ++j) acc[i][j] = fmaf(ar[i], br[j], acc[i][j]);
        }
        __syncthreads();
    }

#pragma unroll
    for (int i = 0; i < 4; ++i) {
        int m = m0 + (ty << 2) + i;
#pragma unroll
        for (int j = 0; j < 4; ++j) {
            int n = n0 + (tx << 2) + j;
            float v = acc[i][j];
            if (Cinit) v += Cinit[(size_t)m * ldc + n];
            if (bias)  v += bias[n];
            C[(size_t)m * ldc + n] = v;
        }
    }
}

// ---------------------------------------------------------------------------
// MHA core per (l, b, h): softmax(q kᵀ / 8 + mask) v ; R=24 rows, dh=64
// One warp per row r; 24 warps (768 threads) per block.
// ---------------------------------------------------------------------------
__global__ __launch_bounds__(768)
void attn_kernel(const float* __restrict__ qkv, const float* __restrict__ mask,
                 float* __restrict__ att) {
    int bid = blockIdx.x;
    int h = bid & 1;
    int b = (bid >> 1) & 63;
    int l = bid >> 7;

    __shared__ float ks[RR][64];
    __shared__ float vs[RR][64];
    int tid = threadIdx.x;
    for (int idx = tid; idx < RR * 64; idx += 768) {
        int s = idx >> 6, d = idx & 63;
        int base = ((l * RR + s) * BB + b) * 384 + h * 64 + d;
        ks[s][d] = qkv[base + 128];
        vs[s][d] = qkv[base + 256];
    }
    __syncthreads();

    int w = tid >> 5, lane = tid & 31;
    if (w >= RR) return;
    int r = w;
    int mq = ((l * RR + r) * BB + b) * 384 + h * 64;
    float q0 = qkv[mq + lane];
    float q1 = qkv[mq + 32 + lane];

    float sc = 0.f;
#pragma unroll
    for (int s = 0; s < RR; ++s) {
        float part = q0 * ks[s][lane] + q1 * ks[s][lane + 32];
#pragma unroll
        for (int off = 16; off; off >>= 1)
            part += __shfl_xor_sync(0xffffffffu, part, off);
        if (lane == s) sc = part;
    }
    float sco = (lane < RR) ? sc * 0.125f + mask[r * RR + lane] : -INFINITY;
    float mx = sco;
#pragma unroll
    for (int off = 16; off; off >>= 1)
        mx = fmaxf(mx, __shfl_xor_sync(0xffffffffu, mx, off));
    float e = expf(sco - mx);               // lanes >= 24 -> exp(-inf) = 0
    float sum = e;
#pragma unroll
    for (int off = 16; off; off >>= 1)
        sum += __shfl_xor_sync(0xffffffffu, sum, off);
    float p = e / sum;

    float acc0 = 0.f, acc1 = 0.f;
#pragma unroll
    for (int s = 0; s < RR; ++s) {
        float ps = __shfl_sync(0xffffffffu, p, s);
        acc0 = fmaf(ps, vs[s][lane], acc0);
        acc1 = fmaf(ps, vs[s][lane + 32], acc1);
    }
    int mo = ((l * RR + r) * BB + b) * EMB + h * 64;
    att[mo + lane] = acc0;
    att[mo + 32 + lane] = acc1;
}

// ---------------------------------------------------------------------------
// Gate / state update / output writes for step s.
// g layout per row m: [ug_r | og_r | ug_c | og_c | ig_r | ig_c] each H=256.
// h layout per row m: [h_row(256) | h_col(256)].
// h_col roll handled by writing new h_col at row (r+1)%RR of hout.
// ---------------------------------------------------------------------------
__global__ __launch_bounds__(256)
void gate_kernel(const float* __restrict__ g,
                 const float* __restrict__ hin,
                 float* __restrict__ hout,
                 const float* __restrict__ Bias,
                 float* __restrict__ out_all,
                 float* __restrict__ out_col,
                 float* __restrict__ out_row,
                 int s) {
    int idx = blockIdx.x * 256 + threadIdx.x;   // M1 * HH threads
    int k = idx & 255;
    int m = idx >> 8;
    int b = m & 63;
    int r = m >> 6;

    const float* grow = g + (size_t)m * 1536;
    float bm = (r <= s && s < RR) ? 1.f : 0.f;

    float ug_r = 1.f / (1.f + expf(-(grow[k]          + bm * Bias[k])));
    float og_r = 1.f / (1.f + expf(-(grow[256 + k]    + bm * Bias[256 + k])));
    float ug_c = 1.f / (1.f + expf(-(grow[512 + k]    + bm * Bias[512 + k])));
    float og_c = 1.f / (1.f + expf(-(grow[768 + k]    + bm * Bias[768 + k])));
    float ig_r = tanhf(grow[1024 + k] + bm * Bias[1024 + k]);
    float ig_c = tanhf(grow[1280 + k] + bm * Bias[1280 + k]);

    float hr_old = hin[m * 512 + k];
    float hc_old = hin[m * 512 + 256 + k];

    float hr = tanhf((1.f - ug_r) * hr_old + ug_r * ig_r) * og_r;
    float hc = tanhf((1.f - ug_c) * hc_old + ug_c * ig_c) * og_c;

    // state for next step (h_col rolled by +1 along r)
    hout[m * 512 + k] = hr;
    int r2 = (r + 1) % RR;
    hout[(r2 * BB + b) * 512 + 256 + k] = hc;

    // output_all[(r*BB+b), s, :]
    float* ob = out_all + ((size_t)m * LSTEPS + s) * 512;
    ob[k] = hr;
    ob[256 + k] = hc;

    if (s >= OO - 1) {
        int t = s - (OO - 1);            // 0..23
        if (r == t)      out_row[(b * RR + t) * HH + k] = hr;
        if (r == RR - 1) out_col[(b * OO + t) * HH + k] = hc;
    }
}

// ---------------------------------------------------------------------------
// Launch
// ---------------------------------------------------------------------------
extern "C" void kernel_launch(void* const* d_in, const int* in_sizes, int n_in,
                              void* d_out, int out_size) {
    const float* input = (const float*)d_in[0];
    const float* mask  = (const float*)d_in[1];
    const float* W     = (const float*)d_in[2];
    const float* Bias  = (const float*)d_in[3];
    const float* inw   = (const float*)d_in[4];
    const float* inb   = (const float*)d_in[5];
    const float* outw  = (const float*)d_in[6];
    const float* outb  = (const float*)d_in[7];
    float* out = (float*)d_out;

    float *a, *qkv, *att, *y, *pre, *h, *g;
    cudaGetSymbolAddress((void**)&a,   d_a);
    cudaGetSymbolAddress((void**)&qkv, d_qkv);
    cudaGetSymbolAddress((void**)&att, d_att);
    cudaGetSymbolAddress((void**)&y,   d_y);
    cudaGetSymbolAddress((void**)&pre, d_pre);
    cudaGetSymbolAddress((void**)&h,   d_h);
    cudaGetSymbolAddress((void**)&g,   d_g);

    // 1) x for all 47 steps
    build_x_kernel<<<(MALL * EMB + 255) / 256, 256>>>(input, a);

    // 2) qkv = x @ in_proj_wᵀ + in_proj_b   (M=72192, N=384, K=128)
    gemm_tn<<<dim3(384 / 64, MALL / 64), 256>>>(a, EMB, inw, EMB, inb, nullptr,
                                                qkv, 384, EMB);

    // 3) attention core (all l, b, h in parallel)
    attn_kernel<<<LSTEPS * BB * 2, 768>>>(qkv, mask, att);

    // 4) y = att @ out_proj_wᵀ + out_proj_b   (N=128, K=128)
    gemm_tn<<<dim3(EMB / 64, MALL / 64), 256>>>(att, EMB, outw, EMB, outb, nullptr,
                                                y, EMB, EMB);

    // 5) pre = x @ W[:,512:640]ᵀ + y @ W[:,640:768]ᵀ   (N=1536, K=128 each)
    gemm_tn<<<dim3(1536 / 64, MALL / 64), 256>>>(a, EMB, W + 512, 768, nullptr,
                                                 nullptr, pre, 1536, EMB);
    gemm_tn<<<dim3(1536 / 64, MALL / 64), 256>>>(y, EMB, W + 640, 768, nullptr,
                                                 pre, pre, 1536, EMB);

    // 6) zero initial state (buffer 0)
    cudaMemsetAsync(h, 0, (size_t)M1 * 512 * sizeof(float));

    // 7) sequential scan: g = pre[s] + [h_row|h_col] @ W[:, :512]ᵀ, then gates
    for (int s = 0; s < LSTEPS; ++s) {
        float* hin  = h + (size_t)(s & 1) * M1 * 512;
        float* hout = h + (size_t)((s + 1) & 1) * M1 * 512;
        gemm_tn<<<dim3(1536 / 64, M1 / 64), 256>>>(hin, 512, W, 768, nullptr,
                                                   pre + (size_t)s * M1 * 1536,
                                                   g, 1536, 512);
        gate_kernel<<<M1 * HH / 256, 256>>>(g, hin, hout, Bias, out,
                                            out + OUT_ALL_ELEMS,
                                            out + OUT_ALL_ELEMS + HID_ELEMS, s);
    }
}

// round 2
// speedup vs baseline: 1.9829x; 1.9829x over previous
#include <cuda_runtime.h>
#include <cmath>

// Problem constants
#define LSTEPS 47      // L = R + O - 1
#define RR 24
#define OO 24
#define BB 64
#define EMB 128
#define HH 256
#define M1 1536        // RR * BB
#define MALL 72192     // LSTEPS * M1

#define OUT_ALL_ELEMS 36962304   // M1 * LSTEPS * 512
#define HID_ELEMS 393216         // BB * 24 * HH

// Scratch
__device__ float d_xy[(size_t)MALL * 256];    // [x | y] packed, K=256 for pre GEMM
__device__ float d_qkv[(size_t)MALL * 384];
__device__ float d_att[(size_t)MALL * 128];
__device__ float d_pre[(size_t)MALL * 1536];
__device__ float d_h[2 * M1 * 512];           // ping-pong [h_row|h_col]
__device__ float d_g[M1 * 1536];

// ---------------------------------------------------------------------------
// build x: xy[m*256 + i] = input[b, l-r, r, i] (zero outside), y filled later
// ---------------------------------------------------------------------------
__global__ void build_x_kernel(const float* __restrict__ input, float* __restrict__ xy) {
    int idx = blockIdx.x * 256 + threadIdx.x;
    if (idx >= MALL * EMB) return;
    int i = idx & 127;
    int m = idx >> 7;
    int b = m & 63;
    int t = m >> 6;
    int r = t % RR;
    int l = t / RR;
    int o = l - r;
    xy[(size_t)m * 256 + i] = (o >= 0 && o < OO) ? input[((b * OO + o) * RR + r) * EMB + i] : 0.f;
}

// ---------------------------------------------------------------------------
// TF32 tensor-core GEMM: C[m,n] = sum_k A[m*lda+k]*Bw[n*ldb+k] (+Cinit)(+bias)
// M, N multiples of 128; K multiple of 16.
// ---------------------------------------------------------------------------
__device__ __forceinline__ unsigned f2tf(float x) {
    unsigned u; asm("cvt.rna.tf32.f32 %0, %1;" : "=r"(u) : "f"(x)); return u;
}

__device__ __forceinline__ void mma_tf32(float* d, const unsigned* a, const unsigned* b) {
    asm volatile(
        "mma.sync.aligned.m16n8k8.row.col.f32.tf32.tf32.f32 "
        "{%0,%1,%2,%3}, {%4,%5,%6,%7}, {%8,%9}, {%0,%1,%2,%3};\n"
        : "+f"(d[0]), "+f"(d[1]), "+f"(d[2]), "+f"(d[3])
        : "r"(a[0]), "r"(a[1]), "r"(a[2]), "r"(a[3]), "r"(b[0]), "r"(b[1]));
}

#define SMST 136   // stride: 136 % 32 == 8 -> conflict-free fragment loads

__global__ __launch_bounds__(256, 2)
void gemm_mma(const float* __restrict__ A, int lda,
              const float* __restrict__ Bw, int ldb,
              const float* __restrict__ bias,
              const float* __restrict__ Cinit,
              float* __restrict__ C, int ldc, int K)
{
    __shared__ unsigned As[16][SMST];   // [k][m]
    __shared__ unsigned Bs[16][SMST];   // [k][n]

    int tid  = threadIdx.x;
    int lane = tid & 31;
    int warp = tid >> 5;
    int wm = (warp >> 2) * 64;          // 2 warps along m
    int wn = (warp & 3) * 32;           // 4 warps along n
    int g  = lane >> 2;                 // group 0..7
    int tg = lane & 3;                  // 0..3
    int m0 = blockIdx.y * 128;
    int n0 = blockIdx.x * 128;

    int lrow = tid & 127;               // 0..127 (32 consecutive per warp)
    int lk   = (tid >> 7) * 8;          // 0 or 8
    const float* Ag = A  + (size_t)(m0 + lrow) * lda + lk;
    const float* Bg = Bw + (size_t)(n0 + lrow) * ldb + lk;

    float acc[4][4][4];
#pragma unroll
    for (int i = 0; i < 4; ++i)
#pragma unroll
        for (int j = 0; j < 4; ++j)
#pragma unroll
            for (int q = 0; q < 4; ++q) acc[i][j][q] = 0.f;

    float4 ra0 = *(const float4*)(Ag);
    float4 ra1 = *(const float4*)(Ag + 4);
    float4 rb0 = *(const float4*)(Bg);
    float4 rb1 = *(const float4*)(Bg + 4);

    for (int k0 = 0; k0 < K; k0 += 16) {
        As[lk + 0][lrow] = f2tf(ra0.x); As[lk + 1][lrow] = f2tf(ra0.y);
        As[lk + 2][lrow] = f2tf(ra0.z); As[lk + 3][lrow] = f2tf(ra0.w);
        As[lk + 4][lrow] = f2tf(ra1.x); As[lk + 5][lrow] = f2tf(ra1.y);
        As[lk + 6][lrow] = f2tf(ra1.z); As[lk + 7][lrow] = f2tf(ra1.w);
        Bs[lk + 0][lrow] = f2tf(rb0.x); Bs[lk + 1][lrow] = f2tf(rb0.y);
        Bs[lk + 2][lrow] = f2tf(rb0.z); Bs[lk + 3][lrow] = f2tf(rb0.w);
        Bs[lk + 4][lrow] = f2tf(rb1.x); Bs[lk + 5][lrow] = f2tf(rb1.y);
        Bs[lk + 6][lrow] = f2tf(rb1.z); Bs[lk + 7][lrow] = f2tf(rb1.w);
        __syncthreads();

        if (k0 + 16 < K) {   // prefetch next K-tile into registers
            ra0 = *(const float4*)(Ag + k0 + 16);
            ra1 = *(const float4*)(Ag + k0 + 20);
            rb0 = *(const float4*)(Bg + k0 + 16);
            rb1 = *(const float4*)(Bg + k0 + 20);
        }

#pragma unroll
        for (int ks = 0; ks < 2; ++ks) {
            const unsigned* ar0 = &As[ks * 8 + tg][0];
            const unsigned* ar1 = &As[ks * 8 + tg + 4][0];
            const unsigned* br0 = &Bs[ks * 8 + tg][0];
            const unsigned* br1 = &Bs[ks * 8 + tg + 4][0];
            unsigned af[4][4], bf[4][2];
#pragma unroll
            for (int i = 0; i < 4; ++i) {
                int r = wm + i * 16 + g;
                af[i][0] = ar0[r];     af[i][1] = ar0[r + 8];
                af[i][2] = ar1[r];     af[i][3] = ar1[r + 8];
            }
#pragma unroll
            for (int j = 0; j < 4; ++j) {
                int c = wn + j * 8 + g;
                bf[j][0] = br0[c];     bf[j][1] = br1[c];
            }
#pragma unroll
            for (int i = 0; i < 4; ++i)
#pragma unroll
                for (int j = 0; j < 4; ++j)
                    mma_tf32(acc[i][j], af[i], bf[j]);
        }
        __syncthreads();
    }

    // Epilogue: c0,c1 at (row, col..col+1), c2,c3 at (row+8, col..col+1)
#pragma unroll
    for (int i = 0; i < 4; ++i) {
        int r0 = m0 + wm + i * 16 + g;
#pragma unroll
        for (int j = 0; j < 4; ++j) {
            int c = n0 + wn + j * 8 + 2 * tg;
            float v0 = acc[i][j][0], v1 = acc[i][j][1];
            float v2 = acc[i][j][2], v3 = acc[i][j][3];
            if (Cinit) {
                float2 p0 = *(const float2*)&Cinit[(size_t)r0 * ldc + c];
                float2 p1 = *(const float2*)&Cinit[(size_t)(r0 + 8) * ldc + c];
                v0 += p0.x; v1 += p0.y; v2 += p1.x; v3 += p1.y;
            }
            if (bias) {
                float2 bb = *(const float2*)&bias[c];
                v0 += bb.x; v1 += bb.y; v2 += bb.x; v3 += bb.y;
            }
            *(float2*)&C[(size_t)r0 * ldc + c]       = make_float2(v0, v1);
            *(float2*)&C[(size_t)(r0 + 8) * ldc + c] = make_float2(v2, v3);
        }
    }
}

// ---------------------------------------------------------------------------
// MHA core per (l, b, h): softmax(q kᵀ / 8 + mask) v ; R=24 rows, dh=64
// ---------------------------------------------------------------------------
__global__ __launch_bounds__(768)
void attn_kernel(const float* __restrict__ qkv, const float* __restrict__ mask,
                 float* __restrict__ att) {
    int bid = blockIdx.x;
    int h = bid & 1;
    int b = (bid >> 1) & 63;
    int l = bid >> 7;

    __shared__ float ks[RR][64];
    __shared__ float vs[RR][64];
    int tid = threadIdx.x;
    for (int idx = tid; idx < RR * 64; idx += 768) {
        int s = idx >> 6, d = idx & 63;
        int base = ((l * RR + s) * BB + b) * 384 + h * 64 + d;
        ks[s][d] = qkv[base + 128];
        vs[s][d] = qkv[base + 256];
    }
    __syncthreads();

    int w = tid >> 5, lane = tid & 31;
    if (w >= RR) return;
    int r = w;
    int mq = ((l * RR + r) * BB + b) * 384 + h * 64;
    float q0 = qkv[mq + lane];
    float q1 = qkv[mq + 32 + lane];

    float sc = 0.f;
#pragma unroll
    for (int s = 0; s < RR; ++s) {
        float part = q0 * ks[s][lane] + q1 * ks[s][lane + 32];
#pragma unroll
        for (int off = 16; off; off >>= 1)
            part += __shfl_xor_sync(0xffffffffu, part, off);
        if (lane == s) sc = part;
    }
    float sco = (lane < RR) ? sc * 0.125f + mask[r * RR + lane] : -INFINITY;
    float mx = sco;
#pragma unroll
    for (int off = 16; off; off >>= 1)
        mx = fmaxf(mx, __shfl_xor_sync(0xffffffffu, mx, off));
    float e = expf(sco - mx);
    float sum = e;
#pragma unroll
    for (int off = 16; off; off >>= 1)
        sum += __shfl_xor_sync(0xffffffffu, sum, off);
    float p = e / sum;

    float acc0 = 0.f, acc1 = 0.f;
#pragma unroll
    for (int s = 0; s < RR; ++s) {
        float ps = __shfl_sync(0xffffffffu, p, s);
        acc0 = fmaf(ps, vs[s][lane], acc0);
        acc1 = fmaf(ps, vs[s][lane + 32], acc1);
    }
    int mo = ((l * RR + r) * BB + b) * EMB + h * 64;
    att[mo + lane] = acc0;
    att[mo + 32 + lane] = acc1;
}

// ---------------------------------------------------------------------------
// Gate / state update / outputs for step s.
// ---------------------------------------------------------------------------
__global__ __launch_bounds__(256)
void gate_kernel(const float* __restrict__ g,
                 const float* __restrict__ hin,
                 float* __restrict__ hout,
                 const float* __restrict__ Bias,
                 float* __restrict__ out_all,
                 float* __restrict__ out_col,
                 float* __restrict__ out_row,
                 int s) {
    int idx = blockIdx.x * 256 + threadIdx.x;   // M1 * HH threads
    int k = idx & 255;
    int m = idx >> 8;
    int b = m & 63;
    int r = m >> 6;

    const float* grow = g + (size_t)m * 1536;
    float bm = (r <= s && s < RR) ? 1.f : 0.f;

    float ug_r = 1.f / (1.f + expf(-(grow[k]          + bm * Bias[k])));
    float og_r = 1.f / (1.f + expf(-(grow[256 + k]    + bm * Bias[256 + k])));
    float ug_c = 1.f / (1.f + expf(-(grow[512 + k]    + bm * Bias[512 + k])));
    float og_c = 1.f / (1.f + expf(-(grow[768 + k]    + bm * Bias[768 + k])));
    float ig_r = tanhf(grow[1024 + k] + bm * Bias[1024 + k]);
    float ig_c = tanhf(grow[1280 + k] + bm * Bias[1280 + k]);

    float hr_old = hin[m * 512 + k];
    float hc_old = hin[m * 512 + 256 + k];

    float hr = tanhf((1.f - ug_r) * hr_old + ug_r * ig_r) * og_r;
    float hc = tanhf((1.f - ug_c) * hc_old + ug_c * ig_c) * og_c;

    hout[m * 512 + k] = hr;
    int r2 = (r + 1) % RR;
    hout[(r2 * BB + b) * 512 + 256 + k] = hc;

    float* ob = out_all + ((size_t)m * LSTEPS + s) * 512;
    ob[k] = hr;
    ob[256 + k] = hc;

    if (s >= OO - 1) {
        int t = s - (OO - 1);
        if (r == t)      out_row[(b * RR + t) * HH + k] = hr;
        if (r == RR - 1) out_col[(b * OO + t) * HH + k] = hc;
    }
}

// ---------------------------------------------------------------------------
// Launch
// ---------------------------------------------------------------------------
extern "C" void kernel_launch(void* const* d_in, const int* in_sizes, int n_in,
                              void* d_out, int out_size) {
    const float* input = (const float*)d_in[0];
    const float* mask  = (const float*)d_in[1];
    const float* W     = (const float*)d_in[2];
    const float* Bias  = (const float*)d_in[3];
    const float* inw   = (const float*)d_in[4];
    const float* inb   = (const float*)d_in[5];
    const float* outw  = (const float*)d_in[6];
    const float* outb  = (const float*)d_in[7];
    float* out = (float*)d_out;

    float *xy, *qkv, *att, *pre, *h, *g;
    cudaGetSymbolAddress((void**)&xy,  d_xy);
    cudaGetSymbolAddress((void**)&qkv, d_qkv);
    cudaGetSymbolAddress((void**)&att, d_att);
    cudaGetSymbolAddress((void**)&pre, d_pre);
    cudaGetSymbolAddress((void**)&h,   d_h);
    cudaGetSymbolAddress((void**)&g,   d_g);

    // 1) x for all 47 steps (into xy[:, :128])
    build_x_kernel<<<(MALL * EMB + 255) / 256, 256>>>(input, xy);

    // 2) qkv = x @ in_proj_wᵀ + in_proj_b   (M=72192, N=384, K=128)
    gemm_mma<<<dim3(384 / 128, MALL / 128), 256>>>(xy, 256, inw, EMB, inb, nullptr,
                                                   qkv, 384, EMB);

    // 3) attention core
    attn_kernel<<<LSTEPS * BB * 2, 768>>>(qkv, mask, att);

    // 4) y = att @ out_proj_wᵀ + out_proj_b  -> xy[:, 128:256]
    gemm_mma<<<dim3(128 / 128, MALL / 128), 256>>>(att, EMB, outw, EMB, outb, nullptr,
                                                   xy + 128, 256, EMB);

    // 5) pre = [x|y] @ W[:, 512:768]ᵀ   (single K=256 pass)
    gemm_mma<<<dim3(1536 / 128, MALL / 128), 256>>>(xy, 256, W + 512, 768, nullptr,
                                                    nullptr, pre, 1536, 256);

    // 6) zero initial state
    cudaMemsetAsync(h, 0, (size_t)M1 * 512 * sizeof(float));

    // 7) sequential scan
    for (int s = 0; s < LSTEPS; ++s) {
        float* hin  = h + (size_t)(s & 1) * M1 * 512;
        float* hout = h + (size_t)((s + 1) & 1) * M1 * 512;
        gemm_mma<<<dim3(1536 / 128, M1 / 128), 256>>>(hin, 512, W, 768, nullptr,
                                                      pre + (size_t)s * M1 * 1536,
                                                      g, 1536, 512);
        gate_kernel<<<M1 * HH / 256, 256>>>(g, hin, hout, Bias, out,
                                            out + OUT_ALL_ELEMS,
                                            out + OUT_ALL_ELEMS + HID_ELEMS, s);
    }
}

// round 3
// speedup vs baseline: 3.4526x; 1.7412x over previous
#include <cuda_runtime.h>
#include <cmath>

// Problem constants
#define LSTEPS 47
#define RR 24
#define OO 24
#define BB 64
#define EMB 128
#define HH 256
#define M1 1536        // RR * BB
#define MALL 72192     // LSTEPS * M1

#define OUT_ALL_ELEMS 36962304   // M1 * LSTEPS * 512
#define HID_ELEMS 393216         // BB * 24 * HH

// Scratch
__device__ float d_xy[(size_t)MALL * 256];    // [x | y] packed tf32, K=256 for pre GEMM
__device__ float d_qkv[(size_t)MALL * 384];
__device__ float d_att[(size_t)MALL * 128];   // tf32-rounded
__device__ float d_pre[(size_t)MALL * 1536];
__device__ float d_h[2 * M1 * 512];           // fp32 state ping-pong [h_row|h_col]
__device__ float d_ht[M1 * 512];              // tf32 mirror of current state (GEMM A)
__device__ float d_g[M1 * 1536];
__device__ float d_Wt[4608 * 768];            // tf32-rounded W
__device__ float d_inwt[384 * 128];
__device__ float d_outwt[128 * 128];

__device__ __forceinline__ unsigned f2tf(float x) {
    unsigned u; asm("cvt.rna.tf32.f32 %0, %1;" : "=r"(u) : "f"(x)); return u;
}
__device__ __forceinline__ float f2tff(float x) { return __uint_as_float(f2tf(x)); }
__device__ __forceinline__ float4 tf4(float4 v) {
    return make_float4(f2tff(v.x), f2tff(v.y), f2tff(v.z), f2tff(v.w));
}

// ---------------------------------------------------------------------------
// tf32 rounding of a buffer (float4 granularity; n4 = n/4)
// ---------------------------------------------------------------------------
__global__ void cvt_kernel(const float* __restrict__ src, float* __restrict__ dst, int n4) {
    int i = blockIdx.x * 256 + threadIdx.x;
    if (i >= n4) return;
    ((float4*)dst)[i] = tf4(((const float4*)src)[i]);
}

// ---------------------------------------------------------------------------
// build x (tf32-rounded): xy[m*256 + i] = input[b, l-r, r, i] (zero outside)
// ---------------------------------------------------------------------------
__global__ void build_x_kernel(const float* __restrict__ input, float* __restrict__ xy) {
    int idx = blockIdx.x * 256 + threadIdx.x;   // MALL*32 threads (float4)
    if (idx >= MALL * 32) return;
    int c = idx & 31;
    int m = idx >> 5;
    int b = m & 63;
    int t = m >> 6;
    int r = t % RR;
    int l = t / RR;
    int o = l - r;
    float4 v = make_float4(0.f, 0.f, 0.f, 0.f);
    if (o >= 0 && o < OO)
        v = tf4(((const float4*)(input + (size_t)((b * OO + o) * RR + r) * EMB))[c]);
    ((float4*)(xy + (size_t)m * 256))[c] = v;
}

// ---------------------------------------------------------------------------
// TF32 MMA GEMM, cp.async 4-stage pipeline, swizzled smem.
// C[m,n] = sum_k A[m*lda+k]*Bw[n*ldb+k] (+Cinit)(+bias)(optionally tf32-round)
// Inputs A, Bw must already be tf32-rounded floats.
// M, N multiples of 128; K multiple of 16 and >= 64.
// ---------------------------------------------------------------------------
__device__ __forceinline__ void mma_tf32(float* d, const unsigned* a, const unsigned* b) {
    asm volatile(
        "mma.sync.aligned.m16n8k8.row.col.f32.tf32.tf32.f32 "
        "{%0,%1,%2,%3}, {%4,%5,%6,%7}, {%8,%9}, {%0,%1,%2,%3};\n"
        : "+f"(d[0]), "+f"(d[1]), "+f"(d[2]), "+f"(d[3])
        : "r"(a[0]), "r"(a[1]), "r"(a[2]), "r"(a[3]), "r"(b[0]), "r"(b[1]));
}

__device__ __forceinline__ void cpasync16(float* dst, const float* src) {
    unsigned saddr = (unsigned)__cvta_generic_to_shared(dst);
    asm volatile("cp.async.cg.shared.global [%0], [%1], 16;\n" :: "r"(saddr), "l"(src));
}

#define STAGE_F 4096   // floats per stage (A 2048 + B 2048)

__global__ __launch_bounds__(256, 2)
void gemm_mma(const float* __restrict__ A, int lda,
              const float* __restrict__ Bw, int ldb,
              const float* __restrict__ bias,
              const float* __restrict__ Cinit,
              float* __restrict__ C, int ldc, int K, int round_out)
{
    extern __shared__ float sm[];
    int tid  = threadIdx.x;
    int lane = tid & 31;
    int warp = tid >> 5;
    int wm = (warp >> 2) * 64;
    int wn = (warp & 3) * 32;
    int g  = lane >> 2;
    int tg = lane & 3;
    int m0 = blockIdx.y * 128;
    int n0 = blockIdx.x * 128;

    // producer: thread -> (row, 16B chunk)
    int prow   = tid >> 2;              // 0..63
    int pchunk = (tid & 3) << 2;        // 0,4,8,12
    int psw    = ((prow >> 1) & 3) << 2;
    int dA = prow * 16 + (pchunk ^ psw);     // same offset for row prow+64 (+1024)
    const float* Ag   = A  + (size_t)(m0 + prow) * lda + pchunk;
    const float* Ag64 = Ag + (size_t)64 * lda;
    const float* Bg   = Bw + (size_t)(n0 + prow) * ldb + pchunk;
    const float* Bg64 = Bg + (size_t)64 * ldb;

    auto prefetch = [&](int st, int k0) {
        float* sA = sm + st * STAGE_F;
        float* sB = sA + 2048;
        cpasync16(sA + dA,        Ag   + k0);
        cpasync16(sA + dA + 1024, Ag64 + k0);
        cpasync16(sB + dA,        Bg   + k0);
        cpasync16(sB + dA + 1024, Bg64 + k0);
        asm volatile("cp.async.commit_group;\n" ::);
    };

    float acc[4][4][4];
#pragma unroll
    for (int i = 0; i < 4; ++i)
#pragma unroll
        for (int j = 0; j < 4; ++j)
#pragma unroll
            for (int q = 0; q < 4; ++q) acc[i][j][q] = 0.f;

    int ktiles = K >> 4;
    prefetch(0, 0); prefetch(1, 16); prefetch(2, 32);

    int swz = ((g >> 1) & 3) << 2;     // thread-invariant fragment swizzle

    for (int kt = 0; kt < ktiles; ++kt) {
        asm volatile("cp.async.wait_group 2;\n" ::);
        __syncthreads();
        if (kt + 3 < ktiles) prefetch((kt + 3) & 3, (kt + 3) << 4);
        else asm volatile("cp.async.commit_group;\n" ::);

        const unsigned* sA = (const unsigned*)(sm + (kt & 3) * STAGE_F);
        const unsigned* sB = sA + 2048;
        const unsigned* pA = sA + (wm + g) * 16;
        const unsigned* pB = sB + (wn + g) * 16;

#pragma unroll
        for (int ks = 0; ks < 2; ++ks) {
            int c0  = (ks * 8 + tg) ^ swz;
            int c4  = (ks * 8 + tg + 4) ^ swz;
            unsigned af[4][4], bf[4][2];
#pragma unroll
            for (int i = 0; i < 4; ++i) {
                af[i][0] = pA[i * 256 + c0];
                af[i][1] = pA[i * 256 + 128 + c0];
                af[i][2] = pA[i * 256 + c4];
                af[i][3] = pA[i * 256 + 128 + c4];
            }
#pragma unroll
            for (int j = 0; j < 4; ++j) {
                bf[j][0] = pB[j * 128 + c0];
                bf[j][1] = pB[j * 128 + c4];
            }
#pragma unroll
            for (int i = 0; i < 4; ++i)
#pragma unroll
                for (int j = 0; j < 4; ++j)
                    mma_tf32(acc[i][j], af[i], bf[j]);
        }
    }

    // Epilogue
#pragma unroll
    for (int i = 0; i < 4; ++i) {
        int r0 = m0 + wm + i * 16 + g;
#pragma unroll
        for (int j = 0; j < 4; ++j) {
            int c = n0 + wn + j * 8 + 2 * tg;
            float v0 = acc[i][j][0], v1 = acc[i][j][1];
            float v2 = acc[i][j][2], v3 = acc[i][j][3];
            if (Cinit) {
                float2 p0 = *(const float2*)&Cinit[(size_t)r0 * ldc + c];
                float2 p1 = *(const float2*)&Cinit[(size_t)(r0 + 8) * ldc + c];
                v0 += p0.x; v1 += p0.y; v2 += p1.x; v3 += p1.y;
            }
            if (bias) {
                float2 bb = *(const float2*)&bias[c];
                v0 += bb.x; v1 += bb.y; v2 += bb.x; v3 += bb.y;
            }
            if (round_out) {
                v0 = f2tff(v0); v1 = f2tff(v1); v2 = f2tff(v2); v3 = f2tff(v3);
            }
            *(float2*)&C[(size_t)r0 * ldc + c]       = make_float2(v0, v1);
            *(float2*)&C[(size_t)(r0 + 8) * ldc + c] = make_float2(v2, v3);
        }
    }
}

// ---------------------------------------------------------------------------
// MHA core per (l, b, h): softmax(q kᵀ / 8 + mask) v ; writes tf32-rounded att
// ---------------------------------------------------------------------------
__global__ __launch_bounds__(768)
void attn_kernel(const float* __restrict__ qkv, const float* __restrict__ mask,
                 float* __restrict__ att) {
    int bid = blockIdx.x;
    int h = bid & 1;
    int b = (bid >> 1) & 63;
    int l = bid >> 7;

    __shared__ float ks[RR][64];
    __shared__ float vs[RR][64];
    int tid = threadIdx.x;
    for (int idx = tid; idx < RR * 64; idx += 768) {
        int s = idx >> 6, d = idx & 63;
        int base = ((l * RR + s) * BB + b) * 384 + h * 64 + d;
        ks[s][d] = qkv[base + 128];
        vs[s][d] = qkv[base + 256];
    }
    __syncthreads();

    int w = tid >> 5, lane = tid & 31;
    if (w >= RR) return;
    int r = w;
    int mq = ((l * RR + r) * BB + b) * 384 + h * 64;
    float q0 = qkv[mq + lane];
    float q1 = qkv[mq + 32 + lane];

    float sc = 0.f;
#pragma unroll
    for (int s = 0; s < RR; ++s) {
        float part = q0 * ks[s][lane] + q1 * ks[s][lane + 32];
#pragma unroll
        for (int off = 16; off; off >>= 1)
            part += __shfl_xor_sync(0xffffffffu, part, off);
        if (lane == s) sc = part;
    }
    float sco = (lane < RR) ? sc * 0.125f + mask[r * RR + lane] : -INFINITY;
    float mx = sco;
#pragma unroll
    for (int off = 16; off; off >>= 1)
        mx = fmaxf(mx, __shfl_xor_sync(0xffffffffu, mx, off));
    float e = expf(sco - mx);
    float sum = e;
#pragma unroll
    for (int off = 16; off; off >>= 1)
        sum += __shfl_xor_sync(0xffffffffu, sum, off);
    float p = e / sum;

    float acc0 = 0.f, acc1 = 0.f;
#pragma unroll
    for (int s = 0; s < RR; ++s) {
        float ps = __shfl_sync(0xffffffffu, p, s);
        acc0 = fmaf(ps, vs[s][lane], acc0);
        acc1 = fmaf(ps, vs[s][lane + 32], acc1);
    }
    int mo = ((l * RR + r) * BB + b) * EMB + h * 64;
    att[mo + lane]      = f2tff(acc0);
    att[mo + 32 + lane] = f2tff(acc1);
}

// ---------------------------------------------------------------------------
// Gate / state update / outputs for step s (float4-vectorized).
// Writes fp32 state hout + tf32 mirror ht.
// ---------------------------------------------------------------------------
__global__ __launch_bounds__(256)
void gate_kernel(const float* __restrict__ g,
                 const float* __restrict__ hin,
                 float* __restrict__ hout,
                 float* __restrict__ ht,
                 const float* __restrict__ Bias,
                 float* __restrict__ out_all,
                 float* __restrict__ out_col,
                 float* __restrict__ out_row,
                 int s) {
    int idx = blockIdx.x * 256 + threadIdx.x;   // M1*HH/4 = 98304
    int c = idx & 63;                           // float4 index within 256
    int m = idx >> 6;
    int b = m & 63;
    int r = m >> 6;

    const float4* G = (const float4*)(g + (size_t)m * 1536);
    float4 q[6];
#pragma unroll
    for (int t = 0; t < 6; ++t) q[t] = G[c + t * 64];
    if (r <= s && s < RR) {
        const float4* B4 = (const float4*)Bias;
#pragma unroll
        for (int t = 0; t < 6; ++t) {
            float4 bb = B4[c + t * 64];
            q[t].x += bb.x; q[t].y += bb.y; q[t].z += bb.z; q[t].w += bb.w;
        }
    }
    float* qa = (float*)q;
    float4 hro = ((const float4*)(hin + (size_t)m * 512))[c];
    float4 hco = ((const float4*)(hin + (size_t)m * 512 + 256))[c];
    float* hrp = (float*)&hro;
    float* hcp = (float*)&hco;
    float hr[4], hc[4];
#pragma unroll
    for (int t = 0; t < 4; ++t) {
        float ug_r = 1.f / (1.f + expf(-qa[t]));
        float og_r = 1.f / (1.f + expf(-qa[4 + t]));
        float ug_c = 1.f / (1.f + expf(-qa[8 + t]));
        float og_c = 1.f / (1.f + expf(-qa[12 + t]));
        float ig_r = tanhf(qa[16 + t]);
        float ig_c = tanhf(qa[20 + t]);
        hr[t] = tanhf((1.f - ug_r) * hrp[t] + ug_r * ig_r) * og_r;
        hc[t] = tanhf((1.f - ug_c) * hcp[t] + ug_c * ig_c) * og_c;
    }
    float4 hr4 = make_float4(hr[0], hr[1], hr[2], hr[3]);
    float4 hc4 = make_float4(hc[0], hc[1], hc[2], hc[3]);

    int r2 = (r + 1) % RR;
    int mc = r2 * BB + b;
    ((float4*)(hout + (size_t)m * 512))[c]        = hr4;
    ((float4*)(hout + (size_t)mc * 512 + 256))[c] = hc4;
    ((float4*)(ht + (size_t)m * 512))[c]          = tf4(hr4);
    ((float4*)(ht + (size_t)mc * 512 + 256))[c]   = tf4(hc4);

    float* ob = out_all + ((size_t)m * LSTEPS + s) * 512;
    ((float4*)ob)[c]         = hr4;
    ((float4*)(ob + 256))[c] = hc4;

    if (s >= OO - 1) {
        int t2 = s - (OO - 1);
        if (r == t2)      ((float4*)(out_row + (size_t)(b * RR + t2) * HH))[c] = hr4;
        if (r == RR - 1)  ((float4*)(out_col + (size_t)(b * OO + t2) * HH))[c] = hc4;
    }
}

// ---------------------------------------------------------------------------
// Launch
// ---------------------------------------------------------------------------
extern "C" void kernel_launch(void* const* d_in, const int* in_sizes, int n_in,
                              void* d_out, int out_size) {
    const float* input = (const float*)d_in[0];
    const float* mask  = (const float*)d_in[1];
    const float* W     = (const float*)d_in[2];
    const float* Bias  = (const float*)d_in[3];
    const float* inw   = (const float*)d_in[4];
    const float* inb   = (const float*)d_in[5];
    const float* outw  = (const float*)d_in[6];
    const float* outb  = (const float*)d_in[7];
    float* out = (float*)d_out;

    float *xy, *qkv, *att, *pre, *h, *ht, *g, *Wt, *inwt, *outwt;
    cudaGetSymbolAddress((void**)&xy,    d_xy);
    cudaGetSymbolAddress((void**)&qkv,   d_qkv);
    cudaGetSymbolAddress((void**)&att,   d_att);
    cudaGetSymbolAddress((void**)&pre,   d_pre);
    cudaGetSymbolAddress((void**)&h,     d_h);
    cudaGetSymbolAddress((void**)&ht,    d_ht);
    cudaGetSymbolAddress((void**)&g,     d_g);
    cudaGetSymbolAddress((void**)&Wt,    d_Wt);
    cudaGetSymbolAddress((void**)&inwt,  d_inwt);
    cudaGetSymbolAddress((void**)&outwt, d_outwt);

    cudaFuncSetAttribute(gemm_mma, cudaFuncAttributeMaxDynamicSharedMemorySize, 65536);
    const int SMEMB = 65536;

    // 0) one-time tf32 rounding of weights
    cvt_kernel<<<(4608 * 768 / 4 + 255) / 256, 256>>>(W, Wt, 4608 * 768 / 4);
    cvt_kernel<<<(384 * 128 / 4 + 255) / 256, 256>>>(inw, inwt, 384 * 128 / 4);
    cvt_kernel<<<(128 * 128 / 4 + 255) / 256, 256>>>(outw, outwt, 128 * 128 / 4);

    // 1) x (tf32) for all 47 steps
    build_x_kernel<<<(MALL * 32 + 255) / 256, 256>>>(input, xy);

    // 2) qkv = x @ in_proj_wᵀ + in_proj_b
    gemm_mma<<<dim3(3, MALL / 128), 256, SMEMB>>>(xy, 256, inwt, EMB, inb, nullptr,
                                                  qkv, 384, EMB, 0);

    // 3) attention core (writes tf32 att)
    attn_kernel<<<LSTEPS * BB * 2, 768>>>(qkv, mask, att);

    // 4) y = att @ out_proj_wᵀ + out_proj_b  -> xy[:, 128:256] (tf32)
    gemm_mma<<<dim3(1, MALL / 128), 256, SMEMB>>>(att, EMB, outwt, EMB, outb, nullptr,
                                                  xy + 128, 256, EMB, 1);

    // 5) pre = [x|y] @ W[:, 512:768]ᵀ
    gemm_mma<<<dim3(12, MALL / 128), 256, SMEMB>>>(xy, 256, Wt + 512, 768, nullptr,
                                                   nullptr, pre, 1536, 256, 0);

    // 6) zero initial state (fp32 buffer 0 and tf32 mirror)
    cudaMemsetAsync(h, 0, (size_t)M1 * 512 * sizeof(float));
    cudaMemsetAsync(ht, 0, (size_t)M1 * 512 * sizeof(float));

    // 7) sequential scan
    for (int s = 0; s < LSTEPS; ++s) {
        float* hin  = h + (size_t)(s & 1) * M1 * 512;
        float* hout = h + (size_t)((s + 1) & 1) * M1 * 512;
        gemm_mma<<<dim3(12, 12), 256, SMEMB>>>(ht, 512, Wt, 768, nullptr,
                                               pre + (size_t)s * M1 * 1536,
                                               g, 1536, 512, 0);
        gate_kernel<<<384, 256>>>(g, hin, hout, ht, Bias, out,
                                  out + OUT_ALL_ELEMS,
                                  out + OUT_ALL_ELEMS + HID_ELEMS, s);
    }
}